// round 3
// baseline (speedup 1.0000x reference)
#include <cuda_runtime.h>
#include <cuda_bf16.h>

#define NN 100000
#define EE 1600000
#define DD 128

// ---------------- scratch (device globals; no allocations allowed) ----------
__device__ float g_y[(size_t)NN * DD];      // GEMM output (pre-propagation)
__device__ float g_agg[(size_t)NN * DD];    // layer-1 hidden output
__device__ float g_dout[NN];                // out-degree norm (rsqrt)
__device__ float g_din[NN];                 // in-degree norm (rsqrt)
__device__ int   g_degout[NN];
__device__ int   g_degin[NN];
__device__ int   g_rowstart[NN + 1];        // CSR row offsets (by dst)
__device__ int   g_fill[NN];                // atomic cursors for CSR fill
__device__ int   g_csr[EE];                 // src ids grouped by dst
__device__ int   g_src[EE];
__device__ int   g_dst[EE];
__device__ int   g_is32;

// ---------------- dtype detect: int64 vs int32 edge_index -------------------
__global__ void gcn_detect(const void* ei) {
    __shared__ int bad;
    if (threadIdx.x == 0) bad = 0;
    __syncthreads();
    const long long* p = (const long long*)ei;
    for (int i = threadIdx.x; i < 2048; i += blockDim.x) {
        long long v = p[i];
        if (v < 0 || v >= NN) atomicOr(&bad, 1);
    }
    __syncthreads();
    if (threadIdx.x == 0) g_is32 = bad;
}

// ---------------- decode edges + integer degree histogram -------------------
__global__ void gcn_edges(const void* ei) {
    int e = blockIdx.x * blockDim.x + threadIdx.x;
    if (e >= EE) return;
    int s, d;
    if (g_is32) {
        const int* p = (const int*)ei;
        s = p[e]; d = p[EE + e];
    } else {
        const long long* p = (const long long*)ei;
        s = (int)p[e]; d = (int)p[EE + e];
    }
    g_src[e] = s; g_dst[e] = d;
    atomicAdd(&g_degout[s], 1);
    atomicAdd(&g_degin[d], 1);
}

// ---------------- exclusive scan of in-degrees -> CSR offsets ---------------
__global__ void gcn_scan() {
    __shared__ int sums[1024];
    const int t = threadIdx.x;
    const int CH = (NN + 1023) / 1024;                  // 98
    int lo = t * CH, hi = min(lo + CH, NN);
    int s = 0;
    for (int i = lo; i < hi; i++) s += g_degin[i];
    sums[t] = s;
    __syncthreads();
    for (int off = 1; off < 1024; off <<= 1) {
        int v = (t >= off) ? sums[t - off] : 0;
        __syncthreads();
        sums[t] += v;
        __syncthreads();
    }
    int pre = (t == 0) ? 0 : sums[t - 1];
    for (int i = lo; i < hi; i++) { g_rowstart[i] = pre; pre += g_degin[i]; }
    if (t == 1023) g_rowstart[NN] = sums[1023];
}

// ---------------- CSR fill: group src ids by dst ----------------------------
__global__ void gcn_fill() {
    int e = blockIdx.x * blockDim.x + threadIdx.x;
    if (e >= EE) return;
    int d = g_dst[e];
    int pos = atomicAdd(&g_fill[d], 1);
    g_csr[g_rowstart[d] + pos] = g_src[e];
}

// ---------------- degree -> norm --------------------------------------------
__global__ void gcn_norm() {
    int i = blockIdx.x * blockDim.x + threadIdx.x;
    if (i < NN) {
        g_dout[i] = rsqrtf(fmaxf((float)g_degout[i], 1.f));
        g_din[i]  = rsqrtf(fmaxf((float)g_degin[i],  1.f));
    }
}

// ---------------- GEMM: Y[i,:] = (X[i,:] @ W) * dout[i] ---------------------
// 256 threads: 64 rows x 128 cols per block, thread = 8 rows x 4 cols.
__global__ __launch_bounds__(256, 2) void gcn_gemm(
    const float* __restrict__ X, const float* __restrict__ W,
    float* __restrict__ Y)
{
    __shared__ float Xs[64][36];      // float4 stores at [r][q*4]: 16B-aligned, conflict-free
    __shared__ float Ws[32][DD];

    const int tid = threadIdx.x;
    const int i0  = blockIdx.x * 64;
    const int cx  = tid & 31;             // cols cx*4 .. cx*4+3
    const int r0  = (tid >> 5) * 8;       // rows r0..r0+7 (warp-uniform)

    float acc[8][4];
    #pragma unroll
    for (int i = 0; i < 8; i++)
        acc[i][0] = acc[i][1] = acc[i][2] = acc[i][3] = 0.f;

    for (int kc = 0; kc < DD; kc += 32) {
        #pragma unroll
        for (int t = 0; t < 2; t++) {                 // X tile: 64 x 32
            int id = tid + t * 256;
            int r = id >> 3, q = id & 7;
            int row = i0 + r;
            float4 v = make_float4(0.f, 0.f, 0.f, 0.f);
            if (row < NN) v = *(const float4*)(X + (size_t)row * DD + kc + q * 4);
            *(float4*)&Xs[r][q * 4] = v;
        }
        #pragma unroll
        for (int t = 0; t < 4; t++) {                 // W tile: 32 x 128
            int id = tid + t * 256;
            int k = id >> 5, q = id & 31;
            *(float4*)&Ws[k][q * 4] =
                *(const float4*)(W + (size_t)(kc + k) * DD + q * 4);
        }
        __syncthreads();

        #pragma unroll
        for (int k = 0; k < 32; k++) {
            float4 w = *(const float4*)&Ws[k][cx * 4];
            #pragma unroll
            for (int i = 0; i < 8; i++) {
                float x = Xs[r0 + i][k];              // warp-broadcast LDS
                acc[i][0] = fmaf(x, w.x, acc[i][0]);
                acc[i][1] = fmaf(x, w.y, acc[i][1]);
                acc[i][2] = fmaf(x, w.z, acc[i][2]);
                acc[i][3] = fmaf(x, w.w, acc[i][3]);
            }
        }
        __syncthreads();
    }

    #pragma unroll
    for (int i = 0; i < 8; i++) {
        int row = i0 + r0 + i;
        if (row < NN) {
            float po = g_dout[row];
            float4 o;
            o.x = acc[i][0] * po;
            o.y = acc[i][1] * po;
            o.z = acc[i][2] * po;
            o.w = acc[i][3] * po;
            *(float4*)(Y + (size_t)row * DD + cx * 4) = o;
        }
    }
}

// ---------------- CSR-gather aggregation ------------------------------------
// One warp per dst node: Out[i,:] = din[i] * sum_{e in in(i)} Y[csr[e],:] + bias
// CSR indices fetched 32-wide coalesced, distributed via shfl; gather rows are
// 512B coalesced float4 loads, unrolled 4-deep for MLP.
__global__ __launch_bounds__(256) void gcn_aggregate(
    const float* __restrict__ Yin, float* __restrict__ Out,
    const float* __restrict__ bias)
{
    int warp = (int)((blockIdx.x * (unsigned)blockDim.x + threadIdx.x) >> 5);
    if (warp >= NN) return;
    const int lane = threadIdx.x & 31;
    const int s0 = g_rowstart[warp];
    const int s1 = g_rowstart[warp + 1];

    float4 acc = make_float4(0.f, 0.f, 0.f, 0.f);
    for (int base = s0; base < s1; base += 32) {
        int rem = s1 - base;
        int idx = 0;
        if (lane < rem) idx = g_csr[base + lane];     // one coalesced load / 32 edges
        int cnt = rem < 32 ? rem : 32;
        int j = 0;
        for (; j + 4 <= cnt; j += 4) {
            int a0 = __shfl_sync(0xffffffffu, idx, j);
            int a1 = __shfl_sync(0xffffffffu, idx, j + 1);
            int a2 = __shfl_sync(0xffffffffu, idx, j + 2);
            int a3 = __shfl_sync(0xffffffffu, idx, j + 3);
            float4 v0 = *(const float4*)(Yin + (size_t)a0 * DD + lane * 4);
            float4 v1 = *(const float4*)(Yin + (size_t)a1 * DD + lane * 4);
            float4 v2 = *(const float4*)(Yin + (size_t)a2 * DD + lane * 4);
            float4 v3 = *(const float4*)(Yin + (size_t)a3 * DD + lane * 4);
            acc.x += (v0.x + v1.x) + (v2.x + v3.x);
            acc.y += (v0.y + v1.y) + (v2.y + v3.y);
            acc.z += (v0.z + v1.z) + (v2.z + v3.z);
            acc.w += (v0.w + v1.w) + (v2.w + v3.w);
        }
        for (; j < cnt; j++) {
            int a = __shfl_sync(0xffffffffu, idx, j);
            float4 v = *(const float4*)(Yin + (size_t)a * DD + lane * 4);
            acc.x += v.x; acc.y += v.y; acc.z += v.z; acc.w += v.w;
        }
    }

    float dn = g_din[warp];
    float4 bb = *(const float4*)(bias + lane * 4);
    float4 o;
    o.x = fmaf(acc.x, dn, bb.x);
    o.y = fmaf(acc.y, dn, bb.y);
    o.z = fmaf(acc.z, dn, bb.z);
    o.w = fmaf(acc.w, dn, bb.w);
    *(float4*)(Out + (size_t)warp * DD + lane * 4) = o;
}

// ---------------- launch ------------------------------------------------------
extern "C" void kernel_launch(void* const* d_in, const int* in_sizes, int n_in,
                              void* d_out, int out_size) {
    const float* in_feat = (const float*)d_in[0];
    const void*  ei      = d_in[1];
    const float* W1      = (const float*)d_in[2];
    const float* b1      = (const float*)d_in[3];
    const float* W2      = (const float*)d_in[4];
    const float* b2      = (const float*)d_in[5];
    float*       out     = (float*)d_out;

    const int e_blocks    = (EE + 255) / 256;          // 6250
    const int n_blocks    = (NN + 255) / 256;          // 391
    const int gemm_blocks = (NN + 63) / 64;            // 1563
    const int agg_blocks  = (NN * 32 + 255) / 256;     // 12500 (1 warp/node)

    // zero integer counters via memset nodes (graph-capturable, not kernels)
    void *p_degout, *p_degin, *p_fill;
    cudaGetSymbolAddress(&p_degout, g_degout);
    cudaGetSymbolAddress(&p_degin,  g_degin);
    cudaGetSymbolAddress(&p_fill,   g_fill);
    cudaMemsetAsync(p_degout, 0, NN * sizeof(int));
    cudaMemsetAsync(p_degin,  0, NN * sizeof(int));
    cudaMemsetAsync(p_fill,   0, NN * sizeof(int));

    // graph preprocessing
    gcn_detect<<<1, 256>>>(ei);                 // launch 0
    gcn_edges<<<e_blocks, 256>>>(ei);           // launch 1
    gcn_scan<<<1, 1024>>>();                    // launch 2
    gcn_fill<<<e_blocks, 256>>>();              // launch 3
    gcn_norm<<<n_blocks, 256>>>();              // launch 4

    // layer 1: y1 = (X@W1)*dout ; h1 = din*S(y1) + b1
    gcn_gemm<<<gemm_blocks, 256>>>(in_feat, W1, g_y);          // launch 5
    gcn_aggregate<<<agg_blocks, 256>>>(g_y, g_agg, b1);        // launch 6

    // layer 2: y2 = (h1@W2)*dout ; out = din*S(y2) + b2
    gcn_gemm<<<gemm_blocks, 256>>>(g_agg, W2, g_y);            // launch 7
    gcn_aggregate<<<agg_blocks, 256>>>(g_y, out, b2);          // launch 8
}

// round 4
// speedup vs baseline: 1.0510x; 1.0510x over previous
#include <cuda_runtime.h>
#include <cuda_bf16.h>

#define NN 100000
#define EE 1600000
#define DD 128

// ---------------- scratch (device globals; no allocations allowed) ----------
__device__ float g_y[(size_t)NN * DD];      // GEMM output (pre-propagation)
__device__ float g_agg[(size_t)NN * DD];    // layer-1 hidden output
__device__ int   g_degout[NN];
__device__ int   g_degin[NN];
__device__ int   g_rowstart[NN + 1];        // CSR row offsets (by dst)
__device__ int   g_fill[NN];                // atomic cursors for CSR fill
__device__ int   g_csr[EE];                 // src ids grouped by dst
__device__ int   g_src[EE];
__device__ int   g_dst[EE];
__device__ int   g_is32;

// ---------------- kernel 1: zero counters + dtype detect --------------------
// int64 ids: every 8-byte word in [0, NN). int32 pairs viewed as int64 have a
// random node id in the high word -> out of range almost surely.
__global__ void gcn_zero_detect(const void* ei) {
    int i = blockIdx.x * blockDim.x + threadIdx.x;
    if (i < NN) { g_degout[i] = 0; g_degin[i] = 0; g_fill[i] = 0; }
    if (blockIdx.x == 0) {
        __shared__ int bad;
        if (threadIdx.x == 0) bad = 0;
        __syncthreads();
        const long long* p = (const long long*)ei;
        for (int j = threadIdx.x; j < 2048; j += blockDim.x) {
            long long v = p[j];
            if (v < 0 || v >= NN) atomicOr(&bad, 1);
        }
        __syncthreads();
        if (threadIdx.x == 0) g_is32 = bad;
    }
}

// ---------------- kernel 2: decode edges + integer degree histogram ---------
__global__ void gcn_edges(const void* ei) {
    int e = blockIdx.x * blockDim.x + threadIdx.x;
    if (e >= EE) return;
    int s, d;
    if (g_is32) {
        const int* p = (const int*)ei;
        s = p[e]; d = p[EE + e];
    } else {
        const long long* p = (const long long*)ei;
        s = (int)p[e]; d = (int)p[EE + e];
    }
    g_src[e] = s; g_dst[e] = d;
    atomicAdd(&g_degout[s], 1);
    atomicAdd(&g_degin[d], 1);
}

// ---------------- kernel 3: exclusive scan of in-degrees -> CSR offsets -----
__global__ void gcn_scan() {
    __shared__ int sums[1024];
    const int t = threadIdx.x;
    const int CH = (NN + 1023) / 1024;                  // 98
    int lo = t * CH, hi = min(lo + CH, NN);
    int s = 0;
    for (int i = lo; i < hi; i++) s += g_degin[i];
    sums[t] = s;
    __syncthreads();
    for (int off = 1; off < 1024; off <<= 1) {
        int v = (t >= off) ? sums[t - off] : 0;
        __syncthreads();
        sums[t] += v;
        __syncthreads();
    }
    int pre = (t == 0) ? 0 : sums[t - 1];
    for (int i = lo; i < hi; i++) { g_rowstart[i] = pre; pre += g_degin[i]; }
    if (t == 1023) g_rowstart[NN] = sums[1023];
}

// ---------------- kernel 4 (CAPTURED BY NCU): GEMM --------------------------
// Y[i,:] = (X[i,:] @ W) * rsqrt(max(degout[i],1))
// 256 threads: 64 rows x 128 cols per block; thread = 8 rows x 4 cols.
__global__ __launch_bounds__(256, 2) void gcn_gemm(
    const float* __restrict__ X, const float* __restrict__ W,
    float* __restrict__ Y)
{
    __shared__ float Xs[64][36];      // float4 ops at [r][q*4]: 16B-aligned
    __shared__ float Ws[32][DD];

    const int tid = threadIdx.x;
    const int i0  = blockIdx.x * 64;
    const int cx  = tid & 31;             // cols cx*4 .. cx*4+3
    const int r0  = (tid >> 5) * 8;       // rows r0..r0+7 (warp-uniform)

    float acc[8][4];
    #pragma unroll
    for (int i = 0; i < 8; i++)
        acc[i][0] = acc[i][1] = acc[i][2] = acc[i][3] = 0.f;

    for (int kc = 0; kc < DD; kc += 32) {
        #pragma unroll
        for (int t = 0; t < 2; t++) {                 // X tile: 64 x 32
            int id = tid + t * 256;
            int r = id >> 3, q = id & 7;
            int row = i0 + r;
            float4 v = make_float4(0.f, 0.f, 0.f, 0.f);
            if (row < NN) v = *(const float4*)(X + (size_t)row * DD + kc + q * 4);
            *(float4*)&Xs[r][q * 4] = v;
        }
        #pragma unroll
        for (int t = 0; t < 4; t++) {                 // W tile: 32 x 128
            int id = tid + t * 256;
            int k = id >> 5, q = id & 31;
            *(float4*)&Ws[k][q * 4] =
                *(const float4*)(W + (size_t)(kc + k) * DD + q * 4);
        }
        __syncthreads();

        #pragma unroll
        for (int k4 = 0; k4 < 8; k4++) {              // 4 k-values per step
            float4 xv[8];
            #pragma unroll
            for (int i = 0; i < 8; i++)
                xv[i] = *(const float4*)&Xs[r0 + i][k4 * 4];   // LDS.128 bcast
            #pragma unroll
            for (int kk = 0; kk < 4; kk++) {
                float4 w = *(const float4*)&Ws[k4 * 4 + kk][cx * 4];
                #pragma unroll
                for (int i = 0; i < 8; i++) {
                    float x = (kk == 0) ? xv[i].x : (kk == 1) ? xv[i].y
                            : (kk == 2) ? xv[i].z : xv[i].w;
                    acc[i][0] = fmaf(x, w.x, acc[i][0]);
                    acc[i][1] = fmaf(x, w.y, acc[i][1]);
                    acc[i][2] = fmaf(x, w.z, acc[i][2]);
                    acc[i][3] = fmaf(x, w.w, acc[i][3]);
                }
            }
        }
        __syncthreads();
    }

    #pragma unroll
    for (int i = 0; i < 8; i++) {
        int row = i0 + r0 + i;
        if (row < NN) {
            float po = rsqrtf(fmaxf((float)g_degout[row], 1.f));  // dout inline
            float4 o;
            o.x = acc[i][0] * po;
            o.y = acc[i][1] * po;
            o.z = acc[i][2] * po;
            o.w = acc[i][3] * po;
            *(float4*)(Y + (size_t)row * DD + cx * 4) = o;
        }
    }
}

// ---------------- kernel 5: CSR fill (group src ids by dst) -----------------
__global__ void gcn_fill() {
    int e = blockIdx.x * blockDim.x + threadIdx.x;
    if (e >= EE) return;
    int d = g_dst[e];
    int pos = atomicAdd(&g_fill[d], 1);
    g_csr[g_rowstart[d] + pos] = g_src[e];
}

// ---------------- kernels 6/8: CSR-gather aggregation -----------------------
// One warp per dst node:
//   Out[i,:] = rsqrt(max(degin[i],1)) * sum_{e in in(i)} Y[csr[e],:] + bias
__global__ __launch_bounds__(256) void gcn_aggregate(
    const float* __restrict__ Yin, float* __restrict__ Out,
    const float* __restrict__ bias)
{
    int warp = (int)((blockIdx.x * (unsigned)blockDim.x + threadIdx.x) >> 5);
    if (warp >= NN) return;
    const int lane = threadIdx.x & 31;
    const int s0 = g_rowstart[warp];
    const int s1 = g_rowstart[warp + 1];

    float4 acc = make_float4(0.f, 0.f, 0.f, 0.f);
    for (int base = s0; base < s1; base += 32) {
        int rem = s1 - base;
        int idx = 0;
        if (lane < rem) idx = g_csr[base + lane];     // coalesced index fetch
        int cnt = rem < 32 ? rem : 32;
        int j = 0;
        for (; j + 4 <= cnt; j += 4) {
            int a0 = __shfl_sync(0xffffffffu, idx, j);
            int a1 = __shfl_sync(0xffffffffu, idx, j + 1);
            int a2 = __shfl_sync(0xffffffffu, idx, j + 2);
            int a3 = __shfl_sync(0xffffffffu, idx, j + 3);
            float4 v0 = *(const float4*)(Yin + (size_t)a0 * DD + lane * 4);
            float4 v1 = *(const float4*)(Yin + (size_t)a1 * DD + lane * 4);
            float4 v2 = *(const float4*)(Yin + (size_t)a2 * DD + lane * 4);
            float4 v3 = *(const float4*)(Yin + (size_t)a3 * DD + lane * 4);
            acc.x += (v0.x + v1.x) + (v2.x + v3.x);
            acc.y += (v0.y + v1.y) + (v2.y + v3.y);
            acc.z += (v0.z + v1.z) + (v2.z + v3.z);
            acc.w += (v0.w + v1.w) + (v2.w + v3.w);
        }
        for (; j < cnt; j++) {
            int a = __shfl_sync(0xffffffffu, idx, j);
            float4 v = *(const float4*)(Yin + (size_t)a * DD + lane * 4);
            acc.x += v.x; acc.y += v.y; acc.z += v.z; acc.w += v.w;
        }
    }

    float dn = rsqrtf(fmaxf((float)g_degin[warp], 1.f));   // din inline
    float4 bb = *(const float4*)(bias + lane * 4);
    float4 o;
    o.x = fmaf(acc.x, dn, bb.x);
    o.y = fmaf(acc.y, dn, bb.y);
    o.z = fmaf(acc.z, dn, bb.z);
    o.w = fmaf(acc.w, dn, bb.w);
    *(float4*)(Out + (size_t)warp * DD + lane * 4) = o;
}

// ---------------- launch ------------------------------------------------------
extern "C" void kernel_launch(void* const* d_in, const int* in_sizes, int n_in,
                              void* d_out, int out_size) {
    const float* in_feat = (const float*)d_in[0];
    const void*  ei      = d_in[1];
    const float* W1      = (const float*)d_in[2];
    const float* b1      = (const float*)d_in[3];
    const float* W2      = (const float*)d_in[4];
    const float* b2      = (const float*)d_in[5];
    float*       out     = (float*)d_out;

    const int e_blocks    = (EE + 255) / 256;          // 6250
    const int n_blocks    = (NN + 255) / 256;          // 391
    const int gemm_blocks = (NN + 63) / 64;            // 1563
    const int agg_blocks  = (NN * 32 + 255) / 256;     // 12500 (1 warp/node)

    gcn_zero_detect<<<n_blocks, 256>>>(ei);            // kernel 1
    gcn_edges<<<e_blocks, 256>>>(ei);                  // kernel 2
    gcn_scan<<<1, 1024>>>();                           // kernel 3

    // layer 1 GEMM in ncu capture slot (4th kernel)
    gcn_gemm<<<gemm_blocks, 256>>>(in_feat, W1, g_y);  // kernel 4  <-- captured

    gcn_fill<<<e_blocks, 256>>>();                     // kernel 5
    gcn_aggregate<<<agg_blocks, 256>>>(g_y, g_agg, b1);// kernel 6

    // layer 2
    gcn_gemm<<<gemm_blocks, 256>>>(g_agg, W2, g_y);    // kernel 7
    gcn_aggregate<<<agg_blocks, 256>>>(g_y, out, b2);  // kernel 8
}

// round 6
// speedup vs baseline: 20.5396x; 19.5422x over previous
#include <cuda_runtime.h>
#include <cuda_bf16.h>

#define NN 100000
#define EE 1600000
#define DD 128
#define GRID 148
#define TPB 512
#define NTHREADS (GRID * TPB)
#define NWARPS (GRID * 16)
#define CHN 676                  // ceil(NN / GRID)
#define PT 2                     // ceil(CHN / TPB)
#define TILES 782                // ceil(NN / 128)

// ---------------- scratch (device globals; no allocations allowed) ----------
__device__ float g_y[(size_t)NN * DD];
__device__ float g_agg[(size_t)NN * DD];
__device__ int   g_degout[NN];
__device__ int   g_degin[NN];
__device__ int   g_rowstart[NN + 1];
__device__ int   g_fillc[NN];
__device__ int   g_csr[EE];
__device__ int   g_srcv[EE];
__device__ int   g_dstv[EE];
__device__ int   g_bsum[GRID];
__device__ int   g_boff[GRID];
__device__ int   g_is32;
__device__ int   g_count;                 // barrier arrivals (self-resetting)
__device__ volatile int g_sense;          // barrier release flag (even #bars -> ends 0)

// ---------------- software grid barrier --------------------------------------
// Requires all GRID blocks resident (grid <= #SM, 1 block/SM). Pre-fence makes
// this block's writes L2-visible; post-fence (membar.gl -> CCTL.IVALL) drops
// stale L1 lines before consuming other SMs' data. Even call count per launch
// restores g_sense to 0 for the next graph replay.
__device__ __forceinline__ void grid_barrier(int& parity) {
    int next = parity ^ 1;
    __threadfence();
    __syncthreads();
    if (threadIdx.x == 0) {
        if (atomicAdd(&g_count, 1) == GRID - 1) {
            atomicExch(&g_count, 0);
            __threadfence();
            g_sense = next;
        } else {
            while (g_sense != next) __nanosleep(64);
        }
    }
    __syncthreads();
    __threadfence();
    parity = next;
}

// ---------------- GEMM phase: Y[i,:] = (X[i,:] @ W) * rsqrt(max(degout,1)) --
// 512 threads: 128 rows x 128 cols per tile; thread = 8 rows x 4 cols.
__device__ void gemm_phase(const float* __restrict__ X, const float* __restrict__ W,
                           float* __restrict__ Y) {
    __shared__ float Xs[128][36];         // float4 ops at [r][q*4]: 16B-aligned
    __shared__ float Ws[32][DD];
    const int tid = threadIdx.x;
    const int cx  = tid & 31;             // cols cx*4 .. cx*4+3
    const int r0  = (tid >> 5) * 8;       // rows r0..r0+7 (warp-uniform, 0..120)

    for (int tile = blockIdx.x; tile < TILES; tile += GRID) {
        const int i0 = tile * 128;
        float acc[8][4];
        #pragma unroll
        for (int i = 0; i < 8; i++)
            acc[i][0] = acc[i][1] = acc[i][2] = acc[i][3] = 0.f;

        for (int kc = 0; kc < DD; kc += 32) {
            #pragma unroll
            for (int t = 0; t < 2; t++) {             // X tile: 128 x 32 (1024 float4)
                int id = tid + t * TPB;
                int r = id >> 3, q = id & 7;
                int row = i0 + r;
                float4 v = make_float4(0.f, 0.f, 0.f, 0.f);
                if (row < NN) v = *(const float4*)(X + (size_t)row * DD + kc + q * 4);
                *(float4*)&Xs[r][q * 4] = v;
            }
            #pragma unroll
            for (int t = 0; t < 2; t++) {             // W tile: 32 x 128 (1024 float4)
                int id = tid + t * TPB;
                int k = id >> 5, q = id & 31;
                *(float4*)&Ws[k][q * 4] =
                    *(const float4*)(W + (size_t)(kc + k) * DD + q * 4);
            }
            __syncthreads();

            #pragma unroll
            for (int k = 0; k < 32; k++) {
                float4 w = *(const float4*)&Ws[k][cx * 4];
                #pragma unroll
                for (int i = 0; i < 8; i++) {
                    float x = Xs[r0 + i][k];          // warp-broadcast LDS
                    acc[i][0] = fmaf(x, w.x, acc[i][0]);
                    acc[i][1] = fmaf(x, w.y, acc[i][1]);
                    acc[i][2] = fmaf(x, w.z, acc[i][2]);
                    acc[i][3] = fmaf(x, w.w, acc[i][3]);
                }
            }
            __syncthreads();
        }

        #pragma unroll
        for (int i = 0; i < 8; i++) {
            int row = i0 + r0 + i;
            if (row < NN) {
                float po = rsqrtf(fmaxf((float)g_degout[row], 1.f));
                float4 o;
                o.x = acc[i][0] * po; o.y = acc[i][1] * po;
                o.z = acc[i][2] * po; o.w = acc[i][3] * po;
                *(float4*)(Y + (size_t)row * DD + cx * 4) = o;
            }
        }
    }
}

// ---------------- aggregation phase ------------------------------------------
// One warp per node: Out[i,:] = rsqrt(max(degin,1)) * sum Y[csr[e],:] + bias
__device__ void aggregate_phase(const float* __restrict__ Yin, float* __restrict__ Out,
                                const float* __restrict__ bias) {
    const int lane = threadIdx.x & 31;
    const int gw   = blockIdx.x * (TPB / 32) + (threadIdx.x >> 5);
    float4 bb = *(const float4*)(bias + lane * 4);

    for (int node = gw; node < NN; node += NWARPS) {
        const int s0 = g_rowstart[node];
        const int s1 = g_rowstart[node + 1];
        float4 acc = make_float4(0.f, 0.f, 0.f, 0.f);
        for (int base = s0; base < s1; base += 32) {
            int rem = s1 - base;
            int idx = 0;
            if (lane < rem) idx = g_csr[base + lane];   // coalesced index fetch
            int cnt = rem < 32 ? rem : 32;
            int j = 0;
            for (; j + 4 <= cnt; j += 4) {
                int a0 = __shfl_sync(0xffffffffu, idx, j);
                int a1 = __shfl_sync(0xffffffffu, idx, j + 1);
                int a2 = __shfl_sync(0xffffffffu, idx, j + 2);
                int a3 = __shfl_sync(0xffffffffu, idx, j + 3);
                float4 v0 = *(const float4*)(Yin + (size_t)a0 * DD + lane * 4);
                float4 v1 = *(const float4*)(Yin + (size_t)a1 * DD + lane * 4);
                float4 v2 = *(const float4*)(Yin + (size_t)a2 * DD + lane * 4);
                float4 v3 = *(const float4*)(Yin + (size_t)a3 * DD + lane * 4);
                acc.x += (v0.x + v1.x) + (v2.x + v3.x);
                acc.y += (v0.y + v1.y) + (v2.y + v3.y);
                acc.z += (v0.z + v1.z) + (v2.z + v3.z);
                acc.w += (v0.w + v1.w) + (v2.w + v3.w);
            }
            for (; j < cnt; j++) {
                int a = __shfl_sync(0xffffffffu, idx, j);
                float4 v = *(const float4*)(Yin + (size_t)a * DD + lane * 4);
                acc.x += v.x; acc.y += v.y; acc.z += v.z; acc.w += v.w;
            }
        }
        float dn = rsqrtf(fmaxf((float)g_degin[node], 1.f));
        float4 o;
        o.x = fmaf(acc.x, dn, bb.x);
        o.y = fmaf(acc.y, dn, bb.y);
        o.z = fmaf(acc.z, dn, bb.z);
        o.w = fmaf(acc.w, dn, bb.w);
        *(float4*)(Out + (size_t)node * DD + lane * 4) = o;
    }
}

// ---------------- the single persistent kernel --------------------------------
__global__ __launch_bounds__(TPB) void gcn_mega(
    const float* __restrict__ in_feat, const void* __restrict__ ei,
    const float* __restrict__ W1, const float* __restrict__ b1,
    const float* __restrict__ W2, const float* __restrict__ b2,
    float* __restrict__ out)
{
    __shared__ int si[TPB];
    const int tid  = threadIdx.x;
    const int gtid = blockIdx.x * TPB + tid;
    int parity = 0;

    // ---- P1: zero counters + dtype detect (block 0) ----
    // int64 ids: every 8-byte word in [0, NN). int32 pairs viewed as int64
    // carry a random node id in the high word -> out of range a.s.
    for (int i = gtid; i < NN; i += NTHREADS) {
        g_degout[i] = 0; g_degin[i] = 0; g_fillc[i] = 0;
    }
    if (blockIdx.x == 0) {
        int bad = 0;
        const long long* p = (const long long*)ei;
        for (int j = tid; j < 2048; j += TPB) {
            long long v = p[j];
            if (v < 0 || v >= NN) bad = 1;
        }
        bad = __syncthreads_or(bad);
        if (tid == 0) g_is32 = bad;
    }
    grid_barrier(parity);                                          // B1

    // ---- P2: decode edges + degree histogram ----
    {
        const int is32 = g_is32;
        for (int e = gtid; e < EE; e += NTHREADS) {
            int s, d;
            if (is32) {
                const int* p = (const int*)ei;
                s = p[e]; d = p[EE + e];
            } else {
                const long long* p = (const long long*)ei;
                s = (int)p[e]; d = (int)p[EE + e];
            }
            g_srcv[e] = s; g_dstv[e] = d;
            atomicAdd(&g_degout[s], 1);
            atomicAdd(&g_degin[d], 1);
        }
    }
    grid_barrier(parity);                                          // B2

    // ---- P3: per-block in-degree sums ----
    {
        const int nb = blockIdx.x * CHN;
        const int ne = min(nb + CHN, NN);
        int s = 0;
        for (int i = nb + tid; i < ne; i += TPB) s += g_degin[i];
        si[tid] = s;
        __syncthreads();
        for (int off = TPB / 2; off > 0; off >>= 1) {
            if (tid < off) si[tid] += si[tid + off];
            __syncthreads();
        }
        if (tid == 0) g_bsum[blockIdx.x] = si[0];
    }
    grid_barrier(parity);                                          // B3

    // ---- P4: exclusive scan of 148 block sums (block 0, thread 0) ----
    if (blockIdx.x == 0 && tid == 0) {
        int acc = 0;
        for (int b = 0; b < GRID; b++) { g_boff[b] = acc; acc += g_bsum[b]; }
    }
    grid_barrier(parity);                                          // B4

    // ---- P5: per-block exclusive scan -> g_rowstart ----
    {
        const int nb = blockIdx.x * CHN;
        const int ne = min(nb + CHN, NN);
        const int tb = nb + tid * PT;                 // PT contiguous nodes/thread
        int v0 = 0, v1 = 0;
        if (tb + 0 < ne) v0 = g_degin[tb + 0];
        if (tb + 1 < ne) v1 = g_degin[tb + 1];
        si[tid] = v0 + v1;
        __syncthreads();
        for (int off = 1; off < TPB; off <<= 1) {     // inclusive Hillis-Steele
            int x = (tid >= off) ? si[tid - off] : 0;
            __syncthreads();
            si[tid] += x;
            __syncthreads();
        }
        int excl = ((tid > 0) ? si[tid - 1] : 0) + g_boff[blockIdx.x];
        if (tb + 0 < ne) { g_rowstart[tb + 0] = excl; excl += v0; }
        if (tb + 1 < ne) { g_rowstart[tb + 1] = excl; }
        if (blockIdx.x == 0 && tid == 0) g_rowstart[NN] = EE;
    }
    grid_barrier(parity);                                          // B5

    // ---- P6: CSR fill (group src by dst, atomic cursor) ----
    for (int e = gtid; e < EE; e += NTHREADS) {
        int d = g_dstv[e];
        int pos = atomicAdd(&g_fillc[d], 1);
        g_csr[g_rowstart[d] + pos] = g_srcv[e];
    }
    grid_barrier(parity);                                          // B6

    // ---- P7..P10: two GCN layers ----
    gemm_phase(in_feat, W1, g_y);
    grid_barrier(parity);                                          // B7
    aggregate_phase(g_y, g_agg, b1);
    grid_barrier(parity);                                          // B8
    gemm_phase(g_agg, W2, g_y);
    grid_barrier(parity);                                          // B9
    aggregate_phase(g_y, out, b2);
    grid_barrier(parity);                                          // B10 (parity restore)
}

// ---------------- launch: ONE graph node --------------------------------------
extern "C" void kernel_launch(void* const* d_in, const int* in_sizes, int n_in,
                              void* d_out, int out_size) {
    const float* in_feat = (const float*)d_in[0];
    const void*  ei      = d_in[1];
    const float* W1      = (const float*)d_in[2];
    const float* b1      = (const float*)d_in[3];
    const float* W2      = (const float*)d_in[4];
    const float* b2      = (const float*)d_in[5];
    float*       out     = (float*)d_out;

    gcn_mega<<<GRID, TPB>>>(in_feat, ei, W1, b1, W2, b2, out);
}

// round 8
// speedup vs baseline: 24.0401x; 1.1704x over previous
#include <cuda_runtime.h>
#include <cuda_bf16.h>
#include <cstdint>

#define NN 100000
#define EE 1600000
#define DD 128
#define GRID 148
#define TPB 512
#define NTHREADS (GRID * TPB)
#define NWARPS (GRID * 16)
#define CHN 676                  // ceil(NN / GRID)
#define PT 2                     // ceil(CHN / TPB)
#define TILES 782                // ceil(NN / 128)

// smem layout (bf16, rows padded to SP=136 elems = 272B -> ldmatrix conflict-free)
#define SP 136
#define OFF_XHI 0
#define OFF_XLO 34816
#define OFF_BHI 69632
#define OFF_BLO 104448
#define DSM_BYTES 139264

// ---------------- scratch (device globals; no allocations allowed) ----------
__device__ float g_y[(size_t)NN * DD];
__device__ float g_agg[(size_t)NN * DD];
__device__ int   g_degout[NN];
__device__ int   g_degin[NN];
__device__ int   g_rowstart[NN + 1];
__device__ int   g_fillc[NN];
__device__ int   g_csr[EE];
__device__ int   g_srcv[EE];
__device__ int   g_dstv[EE];
__device__ int   g_bsum[GRID];
__device__ int   g_boff[GRID];
__device__ int   g_is32;
__device__ int   g_count;
__device__ volatile int g_sense;

// ---------------- helpers -----------------------------------------------------
__device__ __forceinline__ uint32_t smem_u32(const void* p) {
    uint32_t a;
    asm("{ .reg .u64 t; cvta.to.shared.u64 t, %1; cvt.u32.u64 %0, t; }" : "=r"(a) : "l"(p));
    return a;
}
__device__ __forceinline__ uint32_t pk2(float a, float b) {   // low half = a
    __nv_bfloat162 t = __floats2bfloat162_rn(a, b);
    return *reinterpret_cast<uint32_t*>(&t);
}
__device__ __forceinline__ void ldsm_x4(uint32_t* r, uint32_t addr) {
    asm volatile("ldmatrix.sync.aligned.m8n8.x4.shared.b16 {%0,%1,%2,%3}, [%4];"
                 : "=r"(r[0]), "=r"(r[1]), "=r"(r[2]), "=r"(r[3]) : "r"(addr));
}
__device__ __forceinline__ void ldsm_x2(uint32_t* r, uint32_t addr) {
    asm volatile("ldmatrix.sync.aligned.m8n8.x2.shared.b16 {%0,%1}, [%2];"
                 : "=r"(r[0]), "=r"(r[1]) : "r"(addr));
}
__device__ __forceinline__ void mma16816(float* d, const uint32_t* a, const uint32_t* b) {
    asm volatile("mma.sync.aligned.m16n8k16.row.col.f32.bf16.bf16.f32 "
                 "{%0,%1,%2,%3}, {%4,%5,%6,%7}, {%8,%9}, {%0,%1,%2,%3};"
                 : "+f"(d[0]), "+f"(d[1]), "+f"(d[2]), "+f"(d[3])
                 : "r"(a[0]), "r"(a[1]), "r"(a[2]), "r"(a[3]), "r"(b[0]), "r"(b[1]));
}

// ---------------- software grid barrier --------------------------------------
__device__ __forceinline__ void grid_barrier(int& parity) {
    int next = parity ^ 1;
    __threadfence();
    __syncthreads();
    if (threadIdx.x == 0) {
        if (atomicAdd(&g_count, 1) == GRID - 1) {
            atomicExch(&g_count, 0);
            __threadfence();
            g_sense = next;
        } else {
            while (g_sense != next) __nanosleep(64);
        }
    }
    __syncthreads();
    __threadfence();
    parity = next;
}

// ---------------- tensor-core GEMM phase (mma.sync bf16x3) --------------------
// Y[i,:] = (X[i,:] @ W) * rsqrt(max(degout[i],1))
// B = W^T stored [n][k] row-major (== col-major B for row.col mma), hi/lo bf16.
__device__ void gemm_tc(const float* __restrict__ X, const float* __restrict__ W,
                        float* __restrict__ Y, char* dsm)
{
    const uint32_t sbase = smem_u32(dsm);
    const int tid  = threadIdx.x;
    const int lane = tid & 31;
    const int wid  = tid >> 5;

    // ---- build B hi/lo once per phase: Bs[n][k] = W[k][n] ----
    for (int idx = tid; idx < DD * DD; idx += TPB) {
        int k = idx >> 7, n = idx & 127;         // idx = k*128 + n, coalesced over n
        float w = W[idx];
        float hf = __bfloat162float(__float2bfloat16(w));
        uint32_t o = (uint32_t)(n * SP + k) * 2u;
        *(__nv_bfloat16*)(dsm + OFF_BHI + o) = __float2bfloat16(hf);
        *(__nv_bfloat16*)(dsm + OFF_BLO + o) = __float2bfloat16(w - hf);
    }
    __syncthreads();

    // warp tile: 32 rows x 32 cols;  wr = wid>>2 (row grp), wc = wid&3 (col grp)
    const int wr = wid >> 2, wc = wid & 3;
    // ldmatrix lane address components
    const uint32_t aRow = (uint32_t)(wr * 32 + (lane & 15));
    const uint32_t aK8  = (uint32_t)((lane >> 4) * 8);
    const uint32_t bN   = (uint32_t)(wc * 32 + (lane & 7));
    const uint32_t bK8  = (uint32_t)((lane & 8) ? 8 : 0);
    // X smem fill mapping: 4 threads per row, 32 cols each
    const int fr = tid >> 2;
    const int fc = (tid & 3) * 32;

    for (int tile = blockIdx.x; tile < TILES; tile += GRID) {
        const int i0 = tile * 128;

        // ---- X tile -> Xhi/Xlo smem ----
        {
            const int row = i0 + fr;
            const bool ok = row < NN;
            const float4* xr = (const float4*)(X + (size_t)(ok ? row : 0) * DD + fc);
            char* ph = dsm + OFF_XHI + (size_t)(fr * SP + fc) * 2;
            char* pl = dsm + OFF_XLO + (size_t)(fr * SP + fc) * 2;
            #pragma unroll
            for (int q = 0; q < 8; q++) {
                float4 v = ok ? xr[q] : make_float4(0.f, 0.f, 0.f, 0.f);
                float hx = __bfloat162float(__float2bfloat16(v.x));
                float hy = __bfloat162float(__float2bfloat16(v.y));
                float hz = __bfloat162float(__float2bfloat16(v.z));
                float hw = __bfloat162float(__float2bfloat16(v.w));
                *(uint2*)(ph + q * 8) = make_uint2(pk2(hx, hy), pk2(hz, hw));
                *(uint2*)(pl + q * 8) = make_uint2(pk2(v.x - hx, v.y - hy),
                                                   pk2(v.z - hz, v.w - hw));
            }
        }
        __syncthreads();

        // ---- 3-pass MMA: Ahi*Bhi + Ahi*Blo + Alo*Bhi ----
        float d[2][4][4];
        #pragma unroll
        for (int mt = 0; mt < 2; mt++)
            #pragma unroll
            for (int nt = 0; nt < 4; nt++)
                #pragma unroll
                for (int q = 0; q < 4; q++) d[mt][nt][q] = 0.f;

        #pragma unroll
        for (int pass = 0; pass < 3; pass++) {
            const uint32_t xs = sbase + ((pass == 2) ? OFF_XLO : OFF_XHI);
            const uint32_t bs = sbase + ((pass == 1) ? OFF_BLO : OFF_BHI);
            #pragma unroll
            for (int kt = 0; kt < 8; kt++) {
                uint32_t a0[4], a1[4];
                ldsm_x4(a0, xs + (aRow * SP + kt * 16 + aK8) * 2);
                ldsm_x4(a1, xs + ((aRow + 16) * SP + kt * 16 + aK8) * 2);
                #pragma unroll
                for (int nt = 0; nt < 4; nt++) {
                    uint32_t b[2];
                    ldsm_x2(b, bs + ((bN + nt * 8) * SP + kt * 16 + bK8) * 2);
                    mma16816(d[0][nt], a0, b);
                    mma16816(d[1][nt], a1, b);
                }
            }
        }

        // ---- epilogue: scale by rsqrt(degout) and store ----
        {
            const int gr = lane >> 2, qc = (lane & 3) * 2;
            #pragma unroll
            for (int mt = 0; mt < 2; mt++) {
                #pragma unroll
                for (int half = 0; half < 2; half++) {
                    int row = i0 + wr * 32 + mt * 16 + gr + half * 8;
                    if (row < NN) {
                        float po = rsqrtf(fmaxf((float)g_degout[row], 1.f));
                        float* yr = Y + (size_t)row * DD + wc * 32 + qc;
                        #pragma unroll
                        for (int nt = 0; nt < 4; nt++) {
                            float2 o;
                            o.x = d[mt][nt][half * 2 + 0] * po;
                            o.y = d[mt][nt][half * 2 + 1] * po;
                            *(float2*)(yr + nt * 8) = o;
                        }
                    }
                }
            }
        }
        __syncthreads();      // protect X smem before next tile overwrites
    }
}

// ---------------- aggregation phase (unchanged, proven) -----------------------
__device__ void aggregate_phase(const float* __restrict__ Yin, float* __restrict__ Out,
                                const float* __restrict__ bias) {
    const int lane = threadIdx.x & 31;
    const int gw   = blockIdx.x * (TPB / 32) + (threadIdx.x >> 5);
    float4 bb = *(const float4*)(bias + lane * 4);

    for (int node = gw; node < NN; node += NWARPS) {
        const int s0 = g_rowstart[node];
        const int s1 = g_rowstart[node + 1];
        float4 acc = make_float4(0.f, 0.f, 0.f, 0.f);
        for (int base = s0; base < s1; base += 32) {
            int rem = s1 - base;
            int idx = 0;
            if (lane < rem) idx = g_csr[base + lane];
            int cnt = rem < 32 ? rem : 32;
            int j = 0;
            for (; j + 4 <= cnt; j += 4) {
                int a0 = __shfl_sync(0xffffffffu, idx, j);
                int a1 = __shfl_sync(0xffffffffu, idx, j + 1);
                int a2 = __shfl_sync(0xffffffffu, idx, j + 2);
                int a3 = __shfl_sync(0xffffffffu, idx, j + 3);
                float4 v0 = *(const float4*)(Yin + (size_t)a0 * DD + lane * 4);
                float4 v1 = *(const float4*)(Yin + (size_t)a1 * DD + lane * 4);
                float4 v2 = *(const float4*)(Yin + (size_t)a2 * DD + lane * 4);
                float4 v3 = *(const float4*)(Yin + (size_t)a3 * DD + lane * 4);
                acc.x += (v0.x + v1.x) + (v2.x + v3.x);
                acc.y += (v0.y + v1.y) + (v2.y + v3.y);
                acc.z += (v0.z + v1.z) + (v2.z + v3.z);
                acc.w += (v0.w + v1.w) + (v2.w + v3.w);
            }
            for (; j < cnt; j++) {
                int a = __shfl_sync(0xffffffffu, idx, j);
                float4 v = *(const float4*)(Yin + (size_t)a * DD + lane * 4);
                acc.x += v.x; acc.y += v.y; acc.z += v.z; acc.w += v.w;
            }
        }
        float dn = rsqrtf(fmaxf((float)g_degin[node], 1.f));
        float4 o;
        o.x = fmaf(acc.x, dn, bb.x);
        o.y = fmaf(acc.y, dn, bb.y);
        o.z = fmaf(acc.z, dn, bb.z);
        o.w = fmaf(acc.w, dn, bb.w);
        *(float4*)(Out + (size_t)node * DD + lane * 4) = o;
    }
}

// ---------------- the single persistent kernel --------------------------------
__global__ __launch_bounds__(TPB) void gcn_mega(
    const float* __restrict__ in_feat, const void* __restrict__ ei,
    const float* __restrict__ W1, const float* __restrict__ b1,
    const float* __restrict__ W2, const float* __restrict__ b2,
    float* __restrict__ out)
{
    extern __shared__ char dsm[];
    __shared__ int si[TPB];
    const int tid  = threadIdx.x;
    const int gtid = blockIdx.x * TPB + tid;
    int parity = 0;

    // ---- P1: zero counters + dtype detect (block 0) ----
    for (int i = gtid; i < NN; i += NTHREADS) {
        g_degout[i] = 0; g_degin[i] = 0; g_fillc[i] = 0;
    }
    if (blockIdx.x == 0) {
        int bad = 0;
        const long long* p = (const long long*)ei;
        for (int j = tid; j < 2048; j += TPB) {
            long long v = p[j];
            if (v < 0 || v >= NN) bad = 1;
        }
        bad = __syncthreads_or(bad);
        if (tid == 0) g_is32 = bad;
    }
    grid_barrier(parity);                                          // B1

    // ---- P2: decode edges + degree histogram ----
    {
        const int is32 = g_is32;
        for (int e = gtid; e < EE; e += NTHREADS) {
            int s, d;
            if (is32) {
                const int* p = (const int*)ei;
                s = p[e]; d = p[EE + e];
            } else {
                const long long* p = (const long long*)ei;
                s = (int)p[e]; d = (int)p[EE + e];
            }
            g_srcv[e] = s; g_dstv[e] = d;
            atomicAdd(&g_degout[s], 1);
            atomicAdd(&g_degin[d], 1);
        }
    }
    grid_barrier(parity);                                          // B2

    // ---- P3: per-block in-degree sums ----
    {
        const int nb = blockIdx.x * CHN;
        const int ne = min(nb + CHN, NN);
        int s = 0;
        for (int i = nb + tid; i < ne; i += TPB) s += g_degin[i];
        si[tid] = s;
        __syncthreads();
        for (int off = TPB / 2; off > 0; off >>= 1) {
            if (tid < off) si[tid] += si[tid + off];
            __syncthreads();
        }
        if (tid == 0) g_bsum[blockIdx.x] = si[0];
    }
    grid_barrier(parity);                                          // B3

    // ---- P4: exclusive scan of block sums ----
    if (blockIdx.x == 0 && tid == 0) {
        int acc = 0;
        for (int b = 0; b < GRID; b++) { g_boff[b] = acc; acc += g_bsum[b]; }
    }
    grid_barrier(parity);                                          // B4

    // ---- P5: per-block exclusive scan -> g_rowstart ----
    {
        const int nb = blockIdx.x * CHN;
        const int ne = min(nb + CHN, NN);
        const int tb = nb + tid * PT;
        int v0 = 0, v1 = 0;
        if (tb + 0 < ne) v0 = g_degin[tb + 0];
        if (tb + 1 < ne) v1 = g_degin[tb + 1];
        si[tid] = v0 + v1;
        __syncthreads();
        for (int off = 1; off < TPB; off <<= 1) {
            int x = (tid >= off) ? si[tid - off] : 0;
            __syncthreads();
            si[tid] += x;
            __syncthreads();
        }
        int excl = ((tid > 0) ? si[tid - 1] : 0) + g_boff[blockIdx.x];
        if (tb + 0 < ne) { g_rowstart[tb + 0] = excl; excl += v0; }
        if (tb + 1 < ne) { g_rowstart[tb + 1] = excl; }
        if (blockIdx.x == 0 && tid == 0) g_rowstart[NN] = EE;
    }
    grid_barrier(parity);                                          // B5

    // ---- P6: CSR fill ----
    for (int e = gtid; e < EE; e += NTHREADS) {
        int d = g_dstv[e];
        int pos = atomicAdd(&g_fillc[d], 1);
        g_csr[g_rowstart[d] + pos] = g_srcv[e];
    }
    grid_barrier(parity);                                          // B6

    // ---- P7..P10: two GCN layers ----
    gemm_tc(in_feat, W1, g_y, dsm);
    grid_barrier(parity);                                          // B7
    aggregate_phase(g_y, g_agg, b1);
    grid_barrier(parity);                                          // B8
    gemm_tc(g_agg, W2, g_y, dsm);
    grid_barrier(parity);                                          // B9
    aggregate_phase(g_y, out, b2);
    grid_barrier(parity);                                          // B10 (parity restore)
}

// ---------------- launch: ONE graph node --------------------------------------
extern "C" void kernel_launch(void* const* d_in, const int* in_sizes, int n_in,
                              void* d_out, int out_size) {
    const float* in_feat = (const float*)d_in[0];
    const void*  ei      = d_in[1];
    const float* W1      = (const float*)d_in[2];
    const float* b1      = (const float*)d_in[3];
    const float* W2      = (const float*)d_in[4];
    const float* b2      = (const float*)d_in[5];
    float*       out     = (float*)d_out;

    cudaFuncSetAttribute(gcn_mega, cudaFuncAttributeMaxDynamicSharedMemorySize, DSM_BYTES);
    gcn_mega<<<GRID, TPB, DSM_BYTES>>>(in_feat, ei, W1, b1, W2, b2, out);
}

// round 9
// speedup vs baseline: 26.2783x; 1.0931x over previous
#include <cuda_runtime.h>
#include <cuda_bf16.h>
#include <cstdint>

#define NN 100000
#define EE 1600000
#define DD 128
#define GRID 148
#define TPB 512
#define NTHREADS (GRID * TPB)
#define NWARPS (GRID * 16)
#define CHN 676                  // ceil(NN / GRID)
#define PT 2                     // ceil(CHN / TPB)
#define TILES 782                // ceil(NN / 128)

// smem layout (bf16, rows padded to SP=136 elems = 272B -> ldmatrix conflict-free)
#define SP 136
#define OFF_XHI 0
#define OFF_XLO 34816
#define OFF_BHI 69632
#define OFF_BLO 104448
#define DSM_BYTES 139264

// ---------------- scratch (device globals; no allocations allowed) ----------
__device__ float g_y[(size_t)NN * DD];
__device__ float g_agg[(size_t)NN * DD];
__device__ int   g_degout[NN];
__device__ int   g_degin[NN];
__device__ int   g_rowstart[NN + 1];
__device__ int   g_fillc[NN];
__device__ int   g_csr[EE];
__device__ int   g_srcv[EE];
__device__ int   g_dstv[EE];
__device__ int   g_bsum[GRID];
__device__ int   g_boff[GRID];
__device__ int   g_is32;
__device__ int   g_count;
__device__ volatile int g_sense;

// ---------------- helpers -----------------------------------------------------
__device__ __forceinline__ uint32_t smem_u32(const void* p) {
    uint32_t a;
    asm("{ .reg .u64 t; cvta.to.shared.u64 t, %1; cvt.u32.u64 %0, t; }" : "=r"(a) : "l"(p));
    return a;
}
__device__ __forceinline__ uint32_t pk2(float a, float b) {   // low half = a
    __nv_bfloat162 t = __floats2bfloat162_rn(a, b);
    return *reinterpret_cast<uint32_t*>(&t);
}
__device__ __forceinline__ void ldsm_x4(uint32_t* r, uint32_t addr) {
    asm volatile("ldmatrix.sync.aligned.m8n8.x4.shared.b16 {%0,%1,%2,%3}, [%4];"
                 : "=r"(r[0]), "=r"(r[1]), "=r"(r[2]), "=r"(r[3]) : "r"(addr));
}
__device__ __forceinline__ void ldsm_x2(uint32_t* r, uint32_t addr) {
    asm volatile("ldmatrix.sync.aligned.m8n8.x2.shared.b16 {%0,%1}, [%2];"
                 : "=r"(r[0]), "=r"(r[1]) : "r"(addr));
}
__device__ __forceinline__ void mma16816(float* d, const uint32_t* a, const uint32_t* b) {
    asm volatile("mma.sync.aligned.m16n8k16.row.col.f32.bf16.bf16.f32 "
                 "{%0,%1,%2,%3}, {%4,%5,%6,%7}, {%8,%9}, {%0,%1,%2,%3};"
                 : "+f"(d[0]), "+f"(d[1]), "+f"(d[2]), "+f"(d[3])
                 : "r"(a[0]), "r"(a[1]), "r"(a[2]), "r"(a[3]), "r"(b[0]), "r"(b[1]));
}

// ---------------- software grid barrier --------------------------------------
__device__ __forceinline__ void grid_barrier(int& parity) {
    int next = parity ^ 1;
    __threadfence();
    __syncthreads();
    if (threadIdx.x == 0) {
        if (atomicAdd(&g_count, 1) == GRID - 1) {
            atomicExch(&g_count, 0);
            __threadfence();
            g_sense = next;
        } else {
            while (g_sense != next) __nanosleep(64);
        }
    }
    __syncthreads();
    __threadfence();
    parity = next;
}

// ---------------- tensor-core GEMM phase (mma.sync bf16x3) --------------------
// Y[i,:] = (X[i,:] @ W) * rsqrt(max(degout[i],1))
// B = W^T stored [n][k] row-major (== col-major B for row.col mma), hi/lo bf16.
__device__ void gemm_tc(const float* __restrict__ X, const float* __restrict__ W,
                        float* __restrict__ Y, char* dsm)
{
    const uint32_t sbase = smem_u32(dsm);
    const int tid  = threadIdx.x;
    const int lane = tid & 31;
    const int wid  = tid >> 5;

    // ---- build B hi/lo once per phase: Bs[n][k] = W[k][n] ----
    for (int idx = tid; idx < DD * DD; idx += TPB) {
        int k = idx >> 7, n = idx & 127;         // idx = k*128 + n, coalesced over n
        float w = W[idx];
        float hf = __bfloat162float(__float2bfloat16(w));
        uint32_t o = (uint32_t)(n * SP + k) * 2u;
        *(__nv_bfloat16*)(dsm + OFF_BHI + o) = __float2bfloat16(hf);
        *(__nv_bfloat16*)(dsm + OFF_BLO + o) = __float2bfloat16(w - hf);
    }
    __syncthreads();

    // warp tile: 32 rows x 32 cols;  wr = wid>>2 (row grp), wc = wid&3 (col grp)
    const int wr = wid >> 2, wc = wid & 3;
    // ldmatrix lane address components
    const uint32_t aRow = (uint32_t)(wr * 32 + (lane & 15));
    const uint32_t aK8  = (uint32_t)((lane >> 4) * 8);
    const uint32_t bN   = (uint32_t)(wc * 32 + (lane & 7));
    const uint32_t bK8  = (uint32_t)((lane & 8) ? 8 : 0);

    for (int tile = blockIdx.x; tile < TILES; tile += GRID) {
        const int i0 = tile * 128;

        // ---- X tile -> Xhi/Xlo smem: warp w owns rows 8w..8w+7 ----
        // Each LDG.128 is one fully-coalesced 512B row segment per warp.
        {
            char* ph = dsm + OFF_XHI + (size_t)lane * 8;
            char* pl = dsm + OFF_XLO + (size_t)lane * 8;
            #pragma unroll
            for (int r = 0; r < 8; r++) {
                int row = i0 + wid * 8 + r;
                bool ok = row < NN;
                float4 v = ok ? *(const float4*)(X + (size_t)row * DD + lane * 4)
                              : make_float4(0.f, 0.f, 0.f, 0.f);
                float hx = __bfloat162float(__float2bfloat16(v.x));
                float hy = __bfloat162float(__float2bfloat16(v.y));
                float hz = __bfloat162float(__float2bfloat16(v.z));
                float hw = __bfloat162float(__float2bfloat16(v.w));
                size_t ro = (size_t)(wid * 8 + r) * SP * 2;
                *(uint2*)(ph + ro) = make_uint2(pk2(hx, hy), pk2(hz, hw));
                *(uint2*)(pl + ro) = make_uint2(pk2(v.x - hx, v.y - hy),
                                                pk2(v.z - hz, v.w - hw));
            }
        }
        __syncthreads();

        // ---- 3-pass MMA: Ahi*Bhi + Ahi*Blo + Alo*Bhi ----
        float d[2][4][4];
        #pragma unroll
        for (int mt = 0; mt < 2; mt++)
            #pragma unroll
            for (int nt = 0; nt < 4; nt++)
                #pragma unroll
                for (int q = 0; q < 4; q++) d[mt][nt][q] = 0.f;

        #pragma unroll
        for (int pass = 0; pass < 3; pass++) {
            const uint32_t xs = sbase + ((pass == 2) ? OFF_XLO : OFF_XHI);
            const uint32_t bs = sbase + ((pass == 1) ? OFF_BLO : OFF_BHI);
            #pragma unroll
            for (int kt = 0; kt < 8; kt++) {
                uint32_t a0[4], a1[4];
                ldsm_x4(a0, xs + (aRow * SP + kt * 16 + aK8) * 2);
                ldsm_x4(a1, xs + ((aRow + 16) * SP + kt * 16 + aK8) * 2);
                #pragma unroll
                for (int nt = 0; nt < 4; nt++) {
                    uint32_t b[2];
                    ldsm_x2(b, bs + ((bN + nt * 8) * SP + kt * 16 + bK8) * 2);
                    mma16816(d[0][nt], a0, b);
                    mma16816(d[1][nt], a1, b);
                }
            }
        }

        // ---- epilogue: scale by rsqrt(degout) and store ----
        {
            const int gr = lane >> 2, qc = (lane & 3) * 2;
            #pragma unroll
            for (int mt = 0; mt < 2; mt++) {
                #pragma unroll
                for (int half = 0; half < 2; half++) {
                    int row = i0 + wr * 32 + mt * 16 + gr + half * 8;
                    if (row < NN) {
                        float po = rsqrtf(fmaxf((float)g_degout[row], 1.f));
                        float* yr = Y + (size_t)row * DD + wc * 32 + qc;
                        #pragma unroll
                        for (int nt = 0; nt < 4; nt++) {
                            float2 o;
                            o.x = d[mt][nt][half * 2 + 0] * po;
                            o.y = d[mt][nt][half * 2 + 1] * po;
                            *(float2*)(yr + nt * 8) = o;
                        }
                    }
                }
            }
        }
        __syncthreads();      // protect X smem before next tile overwrites
    }
}

// ---------------- aggregation phase (MLP-8 gather pipeline) -------------------
__device__ void aggregate_phase(const float* __restrict__ Yin, float* __restrict__ Out,
                                const float* __restrict__ bias) {
    const int lane = threadIdx.x & 31;
    const int gw   = blockIdx.x * (TPB / 32) + (threadIdx.x >> 5);
    float4 bb = *(const float4*)(bias + lane * 4);

    for (int node = gw; node < NN; node += NWARPS) {
        const int s0 = g_rowstart[node];
        const int s1 = g_rowstart[node + 1];
        float4 acc = make_float4(0.f, 0.f, 0.f, 0.f);
        for (int base = s0; base < s1; base += 32) {
            int rem = s1 - base;
            int idx = 0;
            if (lane < rem) idx = g_csr[base + lane];
            int cnt = rem < 32 ? rem : 32;
            int j = 0;
            for (; j + 8 <= cnt; j += 8) {                // 8 outstanding LDG.128
                float4 v[8];
                #pragma unroll
                for (int u = 0; u < 8; u++) {
                    int a = __shfl_sync(0xffffffffu, idx, j + u);
                    v[u] = *(const float4*)(Yin + (size_t)a * DD + lane * 4);
                }
                #pragma unroll
                for (int u = 0; u < 8; u++) {
                    acc.x += v[u].x; acc.y += v[u].y;
                    acc.z += v[u].z; acc.w += v[u].w;
                }
            }
            for (; j + 4 <= cnt; j += 4) {
                float4 v[4];
                #pragma unroll
                for (int u = 0; u < 4; u++) {
                    int a = __shfl_sync(0xffffffffu, idx, j + u);
                    v[u] = *(const float4*)(Yin + (size_t)a * DD + lane * 4);
                }
                #pragma unroll
                for (int u = 0; u < 4; u++) {
                    acc.x += v[u].x; acc.y += v[u].y;
                    acc.z += v[u].z; acc.w += v[u].w;
                }
            }
            for (; j < cnt; j++) {
                int a = __shfl_sync(0xffffffffu, idx, j);
                float4 v = *(const float4*)(Yin + (size_t)a * DD + lane * 4);
                acc.x += v.x; acc.y += v.y; acc.z += v.z; acc.w += v.w;
            }
        }
        float dn = rsqrtf(fmaxf((float)g_degin[node], 1.f));
        float4 o;
        o.x = fmaf(acc.x, dn, bb.x);
        o.y = fmaf(acc.y, dn, bb.y);
        o.z = fmaf(acc.z, dn, bb.z);
        o.w = fmaf(acc.w, dn, bb.w);
        *(float4*)(Out + (size_t)node * DD + lane * 4) = o;
    }
}

// ---------------- the single persistent kernel --------------------------------
__global__ __launch_bounds__(TPB) void gcn_mega(
    const float* __restrict__ in_feat, const void* __restrict__ ei,
    const float* __restrict__ W1, const float* __restrict__ b1,
    const float* __restrict__ W2, const float* __restrict__ b2,
    float* __restrict__ out)
{
    extern __shared__ char dsm[];
    __shared__ int si[TPB];
    const int tid  = threadIdx.x;
    const int gtid = blockIdx.x * TPB + tid;
    int parity = 0;

    // ---- P1: zero counters + dtype detect (block 0) ----
    for (int i = gtid; i < NN; i += NTHREADS) {
        g_degout[i] = 0; g_degin[i] = 0; g_fillc[i] = 0;
    }
    if (blockIdx.x == 0) {
        int bad = 0;
        const long long* p = (const long long*)ei;
        for (int j = tid; j < 2048; j += TPB) {
            long long v = p[j];
            if (v < 0 || v >= NN) bad = 1;
        }
        bad = __syncthreads_or(bad);
        if (tid == 0) g_is32 = bad;
    }
    grid_barrier(parity);                                          // B1

    // ---- P2: decode edges + degree histogram ----
    {
        const int is32 = g_is32;
        for (int e = gtid; e < EE; e += NTHREADS) {
            int s, d;
            if (is32) {
                const int* p = (const int*)ei;
                s = p[e]; d = p[EE + e];
            } else {
                const long long* p = (const long long*)ei;
                s = (int)p[e]; d = (int)p[EE + e];
            }
            g_srcv[e] = s; g_dstv[e] = d;
            atomicAdd(&g_degout[s], 1);
            atomicAdd(&g_degin[d], 1);
        }
    }
    grid_barrier(parity);                                          // B2

    // ---- P3: per-block in-degree sums ----
    {
        const int nb = blockIdx.x * CHN;
        const int ne = min(nb + CHN, NN);
        int s = 0;
        for (int i = nb + tid; i < ne; i += TPB) s += g_degin[i];
        si[tid] = s;
        __syncthreads();
        for (int off = TPB / 2; off > 0; off >>= 1) {
            if (tid < off) si[tid] += si[tid + off];
            __syncthreads();
        }
        if (tid == 0) g_bsum[blockIdx.x] = si[0];
    }
    grid_barrier(parity);                                          // B3

    // ---- P4: exclusive scan of block sums ----
    if (blockIdx.x == 0 && tid == 0) {
        int acc = 0;
        for (int b = 0; b < GRID; b++) { g_boff[b] = acc; acc += g_bsum[b]; }
    }
    grid_barrier(parity);                                          // B4

    // ---- P5: per-block exclusive scan -> g_rowstart ----
    {
        const int nb = blockIdx.x * CHN;
        const int ne = min(nb + CHN, NN);
        const int tb = nb + tid * PT;
        int v0 = 0, v1 = 0;
        if (tb + 0 < ne) v0 = g_degin[tb + 0];
        if (tb + 1 < ne) v1 = g_degin[tb + 1];
        si[tid] = v0 + v1;
        __syncthreads();
        for (int off = 1; off < TPB; off <<= 1) {
            int x = (tid >= off) ? si[tid - off] : 0;
            __syncthreads();
            si[tid] += x;
            __syncthreads();
        }
        int excl = ((tid > 0) ? si[tid - 1] : 0) + g_boff[blockIdx.x];
        if (tb + 0 < ne) { g_rowstart[tb + 0] = excl; excl += v0; }
        if (tb + 1 < ne) { g_rowstart[tb + 1] = excl; }
        if (blockIdx.x == 0 && tid == 0) g_rowstart[NN] = EE;
    }
    grid_barrier(parity);                                          // B5

    // ---- P6: CSR fill ----
    for (int e = gtid; e < EE; e += NTHREADS) {
        int d = g_dstv[e];
        int pos = atomicAdd(&g_fillc[d], 1);
        g_csr[g_rowstart[d] + pos] = g_srcv[e];
    }
    grid_barrier(parity);                                          // B6

    // ---- P7..P10: two GCN layers ----
    gemm_tc(in_feat, W1, g_y, dsm);
    grid_barrier(parity);                                          // B7
    aggregate_phase(g_y, g_agg, b1);
    grid_barrier(parity);                                          // B8
    gemm_tc(g_agg, W2, g_y, dsm);
    grid_barrier(parity);                                          // B9
    aggregate_phase(g_y, out, b2);
    grid_barrier(parity);                                          // B10 (parity restore)
}

// ---------------- launch: ONE graph node --------------------------------------
extern "C" void kernel_launch(void* const* d_in, const int* in_sizes, int n_in,
                              void* d_out, int out_size) {
    const float* in_feat = (const float*)d_in[0];
    const void*  ei      = d_in[1];
    const float* W1      = (const float*)d_in[2];
    const float* b1      = (const float*)d_in[3];
    const float* W2      = (const float*)d_in[4];
    const float* b2      = (const float*)d_in[5];
    float*       out     = (float*)d_out;

    cudaFuncSetAttribute(gcn_mega, cudaFuncAttributeMaxDynamicSharedMemorySize, DSM_BYTES);
    gcn_mega<<<GRID, TPB, DSM_BYTES>>>(in_feat, ei, W1, b1, W2, b2, out);
}